// round 1
// baseline (speedup 1.0000x reference)
#include <cuda_runtime.h>

// DirectConv2d: full cross-correlation (pad = K-1 = 2)
//   inp: [32, 128, 56, 60] f32 (values 0..3)
//   w  : [256, 128, 3, 3]  f32 (values 0..2)
//   out: [32, 256, 58, 62] f32
//
// Implicit GEMM: C[M=256, N=115072] = A[256,1152] * B[1152,115072]
//   A = weight (already row-major in k = ci*9 + kh*3 + kw)
//   B = im2col(inp) with zero-fill halo
// Tiles: BM=128, BN=128, BK=16; 256 threads; 8x8 per-thread microtile
// (split 4+4 in each dim for conflict-free LDS.128).
// All tile counts divide exactly: 115072 = 899*128, 256 = 2*128, 1152 = 72*16.

#define B_    32
#define CIN   128
#define COUT  256
#define H_    56
#define W_    60
#define OH    58
#define OW    62
#define PAD   2
#define IMGPIX (OH * OW)          // 3596
#define GK    (CIN * 9)           // 1152
#define NPIX  (B_ * IMGPIX)       // 115072
#define INIMG (CIN * H_ * W_)     // per-image input elements

#define BM 128
#define BN 128
#define BK 16

__global__ __launch_bounds__(256)
void direct_conv2d_kernel(const float* __restrict__ inp,
                          const float* __restrict__ wgt,
                          float* __restrict__ out)
{
    __shared__ __align__(16) float As[BK][BM + 4];  // [k][m] (transposed weights)
    __shared__ __align__(16) float Bs[BK][BN];      // [k][pixel]

    const int tid = threadIdx.x;
    const int ty  = tid >> 4;      // 0..15 -> m
    const int tx  = tid & 15;      // 0..15 -> n
    const int n0  = blockIdx.x * BN;   // pixel tile origin
    const int m0  = blockIdx.y * BM;   // c_out tile origin

    // ---- per-thread im2col precompute (fixed across k-chunks) ----
    int kk_i[8], pl_i[8], base_in[8], ih0[8], iw0[8];
#pragma unroll
    for (int i = 0; i < 8; i++) {
        int idx = tid + i * 256;         // 0..2047
        int kk  = idx >> 7;              // 0..15  (k within chunk)
        int pl  = idx & 127;             // 0..127 (pixel within tile)
        int p   = n0 + pl;
        int nimg = p / IMGPIX;
        int rem  = p - nimg * IMGPIX;
        int oh   = rem / OW;
        int ow   = rem - oh * OW;
        kk_i[i] = kk;
        pl_i[i] = pl;
        base_in[i] = nimg * INIMG;
        ih0[i] = oh - PAD;
        iw0[i] = ow - PAD;
    }

    // ---- A-tile load precompute ----
    const int arow = tid >> 2;           // 0..63
    const int acol = (tid & 3) * 4;      // 0,4,8,12

    float acc[8][8];
#pragma unroll
    for (int ii = 0; ii < 8; ii++)
#pragma unroll
        for (int jj = 0; jj < 8; jj++) acc[ii][jj] = 0.0f;

    for (int kc = 0; kc < GK; kc += BK) {
        // --- load A tile: weights (contiguous in k), store transposed ---
#pragma unroll
        for (int r0 = 0; r0 < 2; r0++) {
            int row = arow + r0 * 64;
            float4 v = *reinterpret_cast<const float4*>(
                wgt + (size_t)(m0 + row) * GK + kc + acol);
            As[acol + 0][row] = v.x;
            As[acol + 1][row] = v.y;
            As[acol + 2][row] = v.z;
            As[acol + 3][row] = v.w;
        }
        // --- load B tile: im2col gather with halo predication ---
#pragma unroll
        for (int i = 0; i < 8; i++) {
            int k  = kc + kk_i[i];
            int ci = k / 9;
            int t  = k - ci * 9;
            int kh = t / 3;
            int kw = t - kh * 3;
            int ih = ih0[i] + kh;
            int iw = iw0[i] + kw;
            float v = 0.0f;
            if ((unsigned)ih < (unsigned)H_ && (unsigned)iw < (unsigned)W_)
                v = inp[base_in[i] + (ci * H_ + ih) * W_ + iw];
            Bs[kk_i[i]][pl_i[i]] = v;
        }
        __syncthreads();

        // --- compute ---
#pragma unroll
        for (int kk = 0; kk < BK; kk++) {
            float a[8], b[8];
            *reinterpret_cast<float4*>(a)     = *reinterpret_cast<const float4*>(&As[kk][ty * 4]);
            *reinterpret_cast<float4*>(a + 4) = *reinterpret_cast<const float4*>(&As[kk][64 + ty * 4]);
            *reinterpret_cast<float4*>(b)     = *reinterpret_cast<const float4*>(&Bs[kk][tx * 4]);
            *reinterpret_cast<float4*>(b + 4) = *reinterpret_cast<const float4*>(&Bs[kk][64 + tx * 4]);
#pragma unroll
            for (int ii = 0; ii < 8; ii++)
#pragma unroll
                for (int jj = 0; jj < 8; jj++)
                    acc[ii][jj] += a[ii] * b[jj];
        }
        __syncthreads();
    }

    // ---- epilogue: out[nimg][co][oh][ow]; 4-aligned pixel groups never
    //      cross an image boundary (IMGPIX % 4 == 0) -> float4 stores ----
#pragma unroll
    for (int jh = 0; jh < 2; jh++) {
        int p    = n0 + jh * 64 + tx * 4;
        int nimg = p / IMGPIX;
        int rem  = p - nimg * IMGPIX;
        size_t base = (size_t)nimg * (COUT * IMGPIX) + rem;
#pragma unroll
        for (int ii = 0; ii < 8; ii++) {
            int m = m0 + ((ii < 4) ? (ty * 4 + ii) : (64 + ty * 4 + (ii - 4)));
            float4 v = make_float4(acc[ii][jh * 4 + 0], acc[ii][jh * 4 + 1],
                                   acc[ii][jh * 4 + 2], acc[ii][jh * 4 + 3]);
            *reinterpret_cast<float4*>(out + base + (size_t)m * IMGPIX) = v;
        }
    }
}

extern "C" void kernel_launch(void* const* d_in, const int* in_sizes, int n_in,
                              void* d_out, int out_size)
{
    const float* inp = (const float*)d_in[0];
    const float* wgt = (const float*)d_in[1];
    float* out = (float*)d_out;

    dim3 grid(NPIX / BN, COUT / BM);   // 899 x 2
    direct_conv2d_kernel<<<grid, 256>>>(inp, wgt, out);
}

// round 2
// speedup vs baseline: 5.6144x; 5.6144x over previous
#include <cuda_runtime.h>
#include <cuda_bf16.h>
#include <cstdint>

// DirectConv2d full cross-correlation (pad=2):
//   inp [32,128,56,60] f32 (vals 0..3), wgt [256,128,3,3] f32 (vals 0..2)
//   out [32,256,58,62] f32
// Implicit GEMM with reordered K:  k' = (kh*3+kw)*128 + ci   (GK = 1152)
//   C[256, 115072] = A[256,1152] * B[1152,115072]
// bf16 mma.sync.m16n8k16, fp32 accum (exact for these integer values).

#define B_    32
#define CIN   128
#define COUT  256
#define H_    56
#define W_    60
#define OH    58
#define OW    62
#define HW    (H_ * W_)          // 3360
#define IMGPIX (OH * OW)         // 3596
#define GK    (CIN * 9)          // 1152
#define NPIX  (B_ * IMGPIX)      // 115072
#define INIMG (CIN * HW)

#define BM 128
#define BN 128
#define BK 32
#define KITERS (GK / BK)         // 36
#define ROWPAD 40                // bf16 elems per SMEM row (80B: conflict-free ldmatrix phases)
#define TILE_ELEMS (128 * ROWPAD)   // 5120 halfs per tile
#define TILE_U4    (TILE_ELEMS * 2 / 16)  // 640 uint4

// Weights pre-transformed to the exact SMEM tile layout:
// g_wgt_t[mt][it][row][ROWPAD]  (row = m within tile, k' = it*32 + kk)
__device__ __align__(16) __nv_bfloat16 g_wgt_t[2 * KITERS * TILE_ELEMS];

__global__ void prep_weights(const float* __restrict__ wgt)
{
    int idx = blockIdx.x * blockDim.x + threadIdx.x;   // over 2*36*128*32
    if (idx >= 2 * KITERS * 128 * 32) return;
    int kk  = idx & 31;
    int row = (idx >> 5) & 127;
    int v   = idx >> 12;           // 0..71
    int it  = v % KITERS;
    int mt  = v / KITERS;
    int kp  = it * 32 + kk;        // k'
    int tap = kp >> 7;             // 0..8
    int ci  = kp & 127;
    int m   = mt * 128 + row;
    float w = wgt[m * GK + ci * 9 + tap];
    g_wgt_t[((mt * KITERS + it) * 128 + row) * ROWPAD + kk] = __float2bfloat16(w);
}

#define LDSM_X4(R, addr)                                                        \
    asm volatile("ldmatrix.sync.aligned.m8n8.x4.shared.b16 {%0,%1,%2,%3}, [%4];"\
                 : "=r"((R)[0]), "=r"((R)[1]), "=r"((R)[2]), "=r"((R)[3])       \
                 : "r"(addr))

#define MMA16816(C, A, B0, B1)                                                  \
    asm volatile("mma.sync.aligned.m16n8k16.row.col.f32.bf16.bf16.f32 "         \
                 "{%0,%1,%2,%3},{%4,%5,%6,%7},{%8,%9},{%0,%1,%2,%3};"           \
                 : "+f"((C)[0]), "+f"((C)[1]), "+f"((C)[2]), "+f"((C)[3])       \
                 : "r"((A)[0]), "r"((A)[1]), "r"((A)[2]), "r"((A)[3]),          \
                   "r"(B0), "r"(B1))

__global__ __launch_bounds__(256, 2)
void conv_mma_kernel(const float* __restrict__ inp, float* __restrict__ out)
{
    __shared__ __align__(16) __nv_bfloat16 As[2][TILE_ELEMS];
    __shared__ __align__(16) __nv_bfloat16 Bs[2][TILE_ELEMS];

    const int tid    = threadIdx.x;
    const int lane   = tid & 31;
    const int wid    = tid >> 5;
    const int warp_m = wid >> 2;      // 0..1
    const int warp_n = wid & 3;       // 0..3
    const int n0     = blockIdx.x * BN;
    const int mt     = blockIdx.y;

    // ---- B-fill per-thread invariants: thread owns pixel pl, k-halfchunk kset ----
    const int pl   = tid & 127;
    const int kset = tid >> 7;        // 0/1 -> k' offset kset*16 within chunk
    {
    }
    const int p    = n0 + pl;
    const int nimg = p / IMGPIX;
    const int rem  = p - nimg * IMGPIX;
    const int oh   = rem / OW;
    const int ow   = rem - oh * OW;
    const int ih0  = oh - 2;
    const int iw0  = ow - 2;
    const float* inbase = inp + (size_t)nimg * INIMG;

    const uint4* wsrc = reinterpret_cast<const uint4*>(g_wgt_t) + (size_t)mt * KITERS * TILE_U4;

    float acc[4][4][4];
#pragma unroll
    for (int a = 0; a < 4; a++)
#pragma unroll
        for (int b = 0; b < 4; b++)
#pragma unroll
            for (int c = 0; c < 4; c++) acc[a][b][c] = 0.0f;

    // ldmatrix lane addresses (element offsets within a tile)
    const int lrow = lane & 15;
    const int kx   = (lane >> 4) * 8;
    uint32_t a_sm0 = (uint32_t)__cvta_generic_to_shared(
        &As[0][(warp_m * 64 + lrow) * ROWPAD + kx]);
    uint32_t b_sm0 = (uint32_t)__cvta_generic_to_shared(
        &Bs[0][(warp_n * 32 + lrow) * ROWPAD + kx]);
    const uint32_t TILE_BYTES = TILE_ELEMS * 2;

    // B-fill destination
    uint4* dstB0 = reinterpret_cast<uint4*>(&Bs[0][pl * ROWPAD + kset * 16]);
    uint4* dstB1 = reinterpret_cast<uint4*>(&Bs[1][pl * ROWPAD + kset * 16]);

    // ---------------- fill (tile it -> buffer buf) ----------------
    auto fill = [&](int it, int buf) {
        // A: straight copy of pre-transformed tile
        const uint4* src = wsrc + it * TILE_U4;
        uint4* dstA = reinterpret_cast<uint4*>(As[buf]);
#pragma unroll
        for (int i = 0; i < 3; i++) {
            int idx = tid + i * 256;
            if (idx < TILE_U4) dstA[idx] = src[idx];
        }
        // B: im2col gather, tap constant within the 16-k' block
        const int kp0 = it * 32 + kset * 16;
        const int tap = kp0 >> 7;
        const int ci0 = kp0 & 127;
        const int kh  = tap / 3;
        const int kw  = tap - kh * 3;
        const int ih  = ih0 + kh;
        const int iw  = iw0 + kw;
        const bool ok = ((unsigned)ih < (unsigned)H_) && ((unsigned)iw < (unsigned)W_);
        const float* q = inbase + ((size_t)ci0 * H_ + ih) * W_ + iw;
        unsigned r[8];
#pragma unroll
        for (int j = 0; j < 8; j++) {
            float v0 = 0.0f, v1 = 0.0f;
            if (ok) {
                v0 = q[(2 * j) * HW];
                v1 = q[(2 * j + 1) * HW];
            }
            __nv_bfloat162 h = __floats2bfloat162_rn(v0, v1);
            r[j] = *reinterpret_cast<unsigned*>(&h);
        }
        uint4* dB = buf ? dstB1 : dstB0;
        dB[0] = make_uint4(r[0], r[1], r[2], r[3]);
        dB[1] = make_uint4(r[4], r[5], r[6], r[7]);
    };

    // ---------------- compute from buffer buf ----------------
    auto compute = [&](int buf) {
        const uint32_t abase = a_sm0 + buf * TILE_BYTES;
        const uint32_t bbase = b_sm0 + buf * TILE_BYTES;
#pragma unroll
        for (int ks = 0; ks < 2; ks++) {
            const uint32_t ka = abase + ks * 16 * 2;
            const uint32_t kb = bbase + ks * 16 * 2;
            unsigned af[4][4];
#pragma unroll
            for (int mi = 0; mi < 4; mi++)
                LDSM_X4(af[mi], ka + mi * 16 * ROWPAD * 2);
            unsigned bf[2][4];
#pragma unroll
            for (int bi = 0; bi < 2; bi++)
                LDSM_X4(bf[bi], kb + bi * 16 * ROWPAD * 2);
#pragma unroll
            for (int mi = 0; mi < 4; mi++)
#pragma unroll
                for (int nj = 0; nj < 4; nj++) {
                    const int bi = nj >> 1, sub = nj & 1;
                    MMA16816(acc[mi][nj], af[mi], bf[bi][sub], bf[bi][2 + sub]);
                }
        }
    };

    // ---------------- main loop: double buffered ----------------
    fill(0, 0);
    __syncthreads();
#pragma unroll 1
    for (int it = 0; it < KITERS; it++) {
        if (it + 1 < KITERS) fill(it + 1, (it + 1) & 1);
        compute(it & 1);
        __syncthreads();
    }

    // ---------------- epilogue ----------------
    const int g   = lane >> 2;
    const int tig = lane & 3;
#pragma unroll
    for (int nj = 0; nj < 4; nj++) {
        const int p2 = n0 + warp_n * 32 + nj * 8 + tig * 2;
        const int ni = p2 / IMGPIX;
        const int rm = p2 - ni * IMGPIX;
        float* obase = out + (size_t)ni * (COUT * IMGPIX) + rm;
#pragma unroll
        for (int mi = 0; mi < 4; mi++) {
            const int mrow = mt * 128 + warp_m * 64 + mi * 16 + g;
            float2 v0 = make_float2(acc[mi][nj][0], acc[mi][nj][1]);
            float2 v1 = make_float2(acc[mi][nj][2], acc[mi][nj][3]);
            *reinterpret_cast<float2*>(obase + (size_t)mrow * IMGPIX)       = v0;
            *reinterpret_cast<float2*>(obase + (size_t)(mrow + 8) * IMGPIX) = v1;
        }
    }
}

extern "C" void kernel_launch(void* const* d_in, const int* in_sizes, int n_in,
                              void* d_out, int out_size)
{
    const float* inp = (const float*)d_in[0];
    const float* wgt = (const float*)d_in[1];
    float* out = (float*)d_out;

    prep_weights<<<(2 * KITERS * 128 * 32 + 255) / 256, 256>>>(wgt);

    dim3 grid(NPIX / BN, COUT / BM);   // 899 x 2
    conv_mma_kernel<<<grid, 256>>>(inp, out);
}